// round 15
// baseline (speedup 1.0000x reference)
#include <cuda_runtime.h>
#include <math.h>
#include <stdint.h>

// ---------------------------------------------------------------------------
// AttentionEncoderModel on GB300 — R15.
// R11 core (2-stage cp.async tf32 mma GEMM, in-register RNA cvt, attn3)
// + LayerNorm FUSED into the K=256 GEMMs (enc, res1): full 64x256 A-tile
// resident in smem, in-smem row LN, then the standard B-pipeline.
// res1 also emits the normalized stream to gy; res2 uses res=gy.
// Removes all 16 standalone LN launches + their global traffic.
// ---------------------------------------------------------------------------

__device__ float g_a[4096 * 4096];
__device__ float g_b[4096 * 2048];
__device__ float g_x[4096 * 256];
__device__ float g_y[4096 * 256];    // normalized stream (LN2 output)
__device__ float g_c[4096 * 768];
__device__ float g_h[4096 * 1024];
__device__ double g_sum_d, g_sumsq_d;

#define CP16(dst, src) \
    asm volatile("cp.async.ca.shared.global [%0], [%1], 16;" :: "r"(dst), "l"(src))

__device__ __forceinline__ uint32_t f2tf32(float f) {
    uint32_t u;
    asm("cvt.rna.tf32.f32 %0, %1;" : "=r"(u) : "f"(f));
    return u;
}

#define MMA_TF32(acc, a0, a1, a2, a3, b0, b1) \
    asm volatile( \
        "mma.sync.aligned.m16n8k8.row.col.f32.tf32.tf32.f32 " \
        "{%0,%1,%2,%3}, {%4,%5,%6,%7}, {%8,%9}, {%0,%1,%2,%3};" \
        : "+f"((acc)[0]), "+f"((acc)[1]), "+f"((acc)[2]), "+f"((acc)[3]) \
        : "r"(a0), "r"(a1), "r"(a2), "r"(a3), "r"(b0), "r"(b1))

__device__ __forceinline__ float apply_act(float v, int ACT) {
    if (ACT == 1) return fmaxf(v, 0.0f);
    if (ACT == 2) return tanhf(v);
    if (ACT == 3) return 0.5f * v * (1.0f + erff(v * 0.70710678118654752f));
    return v;
}

// ===========================================================================
// tf32 GEMM, tiles BMT x 128 x 32, 256 threads, 2-stage cp.async (R11-exact).
// ===========================================================================
template <int BMT, int ACT, bool HASRES, bool HASPOS>
__global__ __launch_bounds__(256, 2)
void tgemm_k(const float* __restrict__ A, const float* __restrict__ W,
             const float* __restrict__ bias, const float* __restrict__ res,
             const float* __restrict__ pos, float* __restrict__ C,
             int M, int N, int K)
{
    constexpr int AM = BMT / 32;
    extern __shared__ float dynsmem[];
    float* As_ = dynsmem;                   // [2][BMT][36]
    float* Bs_ = dynsmem + 2 * BMT * 36;    // [2][32][136]

    const int tid = threadIdx.x;
    const int lane = tid & 31, wid = tid >> 5;
    const int wm = wid >> 2, wn = wid & 3;
    const int m0 = blockIdx.y * BMT, n0 = blockIdx.x * 128;

    float acc[AM][4][4] = {};

    const int arow = tid >> 3, acol = (tid & 7) * 4;
    const int brow = tid >> 5, bcol = (tid & 31) * 4;

    const uint32_t sA = (uint32_t)__cvta_generic_to_shared(As_);
    const uint32_t sB = (uint32_t)__cvta_generic_to_shared(Bs_);

    const int ntiles = K >> 5;

    auto issue = [&](int t, int buf) {
        int kbase = t * 32;
#pragma unroll
        for (int r = 0; r < AM; r++) {
            uint32_t d = sA + (uint32_t)(((buf * BMT) + arow + r * 32) * 36 + acol) * 4u;
            const float* s = A + (size_t)(m0 + arow + r * 32) * K + kbase + acol;
            CP16(d, s);
        }
#pragma unroll
        for (int r = 0; r < 4; r++) {
            uint32_t d = sB + (uint32_t)(((buf * 32) + brow + r * 8) * 136 + bcol) * 4u;
            const float* s = W + (size_t)(kbase + brow + r * 8) * N + n0 + bcol;
            CP16(d, s);
        }
        asm volatile("cp.async.commit_group;");
    };

    issue(0, 0);

    for (int t = 0; t < ntiles; t++) {
        int cur = t & 1;
        asm volatile("cp.async.wait_group 0;");
        __syncthreads();
        if (t + 1 < ntiles) issue(t + 1, cur ^ 1);

        const float* Ab = As_ + (size_t)cur * BMT * 36;
        const float* Bb = Bs_ + (size_t)cur * 32 * 136;

#pragma unroll
        for (int ks = 0; ks < 4; ks++) {
            int kk = ks * 8;
            uint32_t af[AM][4], bf[4][2];
#pragma unroll
            for (int am = 0; am < AM; am++) {
                int row = wm * (BMT / 2) + am * 16 + (lane >> 2);
                int k = kk + (lane & 3);
                af[am][0] = f2tf32(Ab[row * 36 + k]);
                af[am][1] = f2tf32(Ab[(row + 8) * 36 + k]);
                af[am][2] = f2tf32(Ab[row * 36 + k + 4]);
                af[am][3] = f2tf32(Ab[(row + 8) * 36 + k + 4]);
            }
#pragma unroll
            for (int an = 0; an < 4; an++) {
                int col = wn * 32 + an * 8 + (lane >> 2);
                int k = kk + (lane & 3);
                bf[an][0] = f2tf32(Bb[k * 136 + col]);
                bf[an][1] = f2tf32(Bb[(k + 4) * 136 + col]);
            }
#pragma unroll
            for (int am = 0; am < AM; am++)
#pragma unroll
                for (int an = 0; an < 4; an++)
                    MMA_TF32(acc[am][an], af[am][0], af[am][1], af[am][2], af[am][3],
                             bf[an][0], bf[an][1]);
        }
        __syncthreads();
    }

#pragma unroll
    for (int am = 0; am < AM; am++) {
#pragma unroll
        for (int an = 0; an < 4; an++) {
            int row = m0 + wm * (BMT / 2) + am * 16 + (lane >> 2);
            int col = n0 + wn * 32 + an * 8 + ((lane & 3) << 1);
            float b0 = bias[col], b1 = bias[col + 1];
#pragma unroll
            for (int h = 0; h < 2; h++) {
                int m = row + h * 8;
                float v0 = apply_act(acc[am][an][h * 2 + 0] + b0, ACT);
                float v1 = apply_act(acc[am][an][h * 2 + 1] + b1, ACT);
                if (HASRES) {
                    float2 rr = *(const float2*)(res + (size_t)m * N + col);
                    v0 += rr.x; v1 += rr.y;
                }
                if (HASPOS) {
                    float2 pp = *(const float2*)(pos + (size_t)(m & 511) * N + col);
                    v0 += pp.x; v1 += pp.y;
                }
                *(float2*)(C + (size_t)m * N + col) = make_float2(v0, v1);
            }
        }
    }
}

// ===========================================================================
// Fused LayerNorm + tf32 GEMM, K=256 fixed, tile 64 x 128, 256 threads.
// Full A-tile (64x256) resident in smem; in-smem row LN; B double-buffered.
// WRITEBACK: CTAs with blockIdx.x==0 also store normalized rows to Y.
// C = act(LN(X) @ W + bias)
// ===========================================================================
template <int ACT, bool WRITEBACK>
__global__ __launch_bounds__(256, 2)
void tgemm_ln_k(const float* __restrict__ X, const float* __restrict__ W,
                const float* __restrict__ bias,
                const float* __restrict__ lng, const float* __restrict__ lnb,
                float* __restrict__ C, float* __restrict__ Y, int N)
{
    constexpr int K = 256;
    constexpr int XP = 260;                 // row pad for conflict-free frags
    extern __shared__ float dynsmem[];
    float* Xs = dynsmem;                    // [64][260]
    float* Bs_ = dynsmem + 64 * XP;         // [2][32][136]

    const int tid = threadIdx.x;
    const int lane = tid & 31, wid = tid >> 5;
    const int wm = wid >> 2, wn = wid & 3;  // 2 x 4 warps, warp tile 32x32
    const int m0 = blockIdx.y * 64, n0 = blockIdx.x * 128;

    const int brow = tid >> 5, bcol = (tid & 31) * 4;

    const uint32_t sX = (uint32_t)__cvta_generic_to_shared(Xs);
    const uint32_t sB = (uint32_t)__cvta_generic_to_shared(Bs_);

    auto issueB = [&](int t, int buf) {
        int kbase = t * 32;
#pragma unroll
        for (int r = 0; r < 4; r++) {
            uint32_t d = sB + (uint32_t)(((buf * 32) + brow + r * 8) * 136 + bcol) * 4u;
            CP16(d, W + (size_t)(kbase + brow + r * 8) * N + n0 + bcol);
        }
        asm volatile("cp.async.commit_group;");
    };

    // copy the whole 64x256 A tile (16 cp.async per thread) + B tile 0
    {
#pragma unroll
        for (int i = 0; i < 16; i++) {
            int f4 = tid + i * 256;         // float4 index, 4096 total
            int row = f4 >> 6;
            int c4 = f4 & 63;
            uint32_t d = sX + (uint32_t)(row * XP + c4 * 4) * 4u;
            CP16(d, X + (size_t)(m0 + row) * K + c4 * 4);
        }
#pragma unroll
        for (int r = 0; r < 4; r++) {
            uint32_t d = sB + (uint32_t)((brow + r * 8) * 136 + bcol) * 4u;
            CP16(d, W + (size_t)(brow + r * 8) * N + n0 + bcol);
        }
        asm volatile("cp.async.commit_group;");
    }
    asm volatile("cp.async.wait_group 0;");
    __syncthreads();

    // in-smem LayerNorm: warp wid handles rows wid*8 .. wid*8+7
    {
        int lane4 = lane * 4;
        float4 gg0 = *(const float4*)(lng + lane4);
        float4 gg1 = *(const float4*)(lng + 128 + lane4);
        float4 bb0 = *(const float4*)(lnb + lane4);
        float4 bb1 = *(const float4*)(lnb + 128 + lane4);
#pragma unroll
        for (int j = 0; j < 8; j++) {
            int r = wid * 8 + j;
            float* rp = Xs + r * XP;
            float4 v0 = *(float4*)(rp + lane4);
            float4 v1 = *(float4*)(rp + 128 + lane4);
            float s = v0.x + v0.y + v0.z + v0.w + v1.x + v1.y + v1.z + v1.w;
#pragma unroll
            for (int o = 16; o > 0; o >>= 1) s += __shfl_xor_sync(0xffffffffu, s, o);
            float mean = s * (1.0f / 256.0f);
            float d0x = v0.x - mean, d0y = v0.y - mean, d0z = v0.z - mean, d0w = v0.w - mean;
            float d1x = v1.x - mean, d1y = v1.y - mean, d1z = v1.z - mean, d1w = v1.w - mean;
            float ss = d0x * d0x + d0y * d0y + d0z * d0z + d0w * d0w
                     + d1x * d1x + d1y * d1y + d1z * d1z + d1w * d1w;
#pragma unroll
            for (int o = 16; o > 0; o >>= 1) ss += __shfl_xor_sync(0xffffffffu, ss, o);
            float inv = rsqrtf(ss * (1.0f / 256.0f) + 1e-5f);
            *(float4*)(rp + lane4) = make_float4(
                d0x * inv * gg0.x + bb0.x, d0y * inv * gg0.y + bb0.y,
                d0z * inv * gg0.z + bb0.z, d0w * inv * gg0.w + bb0.w);
            *(float4*)(rp + 128 + lane4) = make_float4(
                d1x * inv * gg1.x + bb1.x, d1y * inv * gg1.y + bb1.y,
                d1z * inv * gg1.z + bb1.z, d1w * inv * gg1.w + bb1.w);
        }
    }
    __syncthreads();

    float acc[2][4][4] = {};

    // mainloop: 8 B k-tiles, R11 2-stage pattern
    for (int t = 0; t < 8; t++) {
        int cur = t & 1;
        if (t > 0) {
            asm volatile("cp.async.wait_group 0;");
            __syncthreads();
        } else {
            // B0 issued above in group with A? No: B0 was in the A group and
            // already waited+synced. Issue B1 now.
        }
        if (t + 1 < 8) issueB(t + 1, cur ^ 1);

        const float* Bb = Bs_ + (size_t)cur * 32 * 136;
        int kt = t * 32;

#pragma unroll
        for (int ks = 0; ks < 4; ks++) {
            int kk = kt + ks * 8;
            uint32_t af[2][4], bf[4][2];
#pragma unroll
            for (int am = 0; am < 2; am++) {
                int row = wm * 32 + am * 16 + (lane >> 2);
                int k = kk + (lane & 3);
                af[am][0] = f2tf32(Xs[row * XP + k]);
                af[am][1] = f2tf32(Xs[(row + 8) * XP + k]);
                af[am][2] = f2tf32(Xs[row * XP + k + 4]);
                af[am][3] = f2tf32(Xs[(row + 8) * XP + k + 4]);
            }
#pragma unroll
            for (int an = 0; an < 4; an++) {
                int col = wn * 32 + an * 8 + (lane >> 2);
                int k = ks * 8 + (lane & 3);
                bf[an][0] = f2tf32(Bb[k * 136 + col]);
                bf[an][1] = f2tf32(Bb[(k + 4) * 136 + col]);
            }
#pragma unroll
            for (int am = 0; am < 2; am++)
#pragma unroll
                for (int an = 0; an < 4; an++)
                    MMA_TF32(acc[am][an], af[am][0], af[am][1], af[am][2], af[am][3],
                             bf[an][0], bf[an][1]);
        }
        __syncthreads();
    }

    // writeback of normalized rows (res1 path): one CTA column only
    if (WRITEBACK && blockIdx.x == 0) {
#pragma unroll
        for (int i = 0; i < 16; i++) {
            int f4 = tid + i * 256;
            int row = f4 >> 6;
            int c4 = f4 & 63;
            *(float4*)(Y + (size_t)(m0 + row) * K + c4 * 4) =
                *(float4*)(Xs + row * XP + c4 * 4);
        }
    }

    // epilogue
#pragma unroll
    for (int am = 0; am < 2; am++) {
#pragma unroll
        for (int an = 0; an < 4; an++) {
            int row = m0 + wm * 32 + am * 16 + (lane >> 2);
            int col = n0 + wn * 32 + an * 8 + ((lane & 3) << 1);
            float b0 = bias[col], b1 = bias[col + 1];
#pragma unroll
            for (int h = 0; h < 2; h++) {
                int m = row + h * 8;
                float v0 = apply_act(acc[am][an][h * 2 + 0] + b0, ACT);
                float v1 = apply_act(acc[am][an][h * 2 + 1] + b1, ACT);
                *(float2*)(C + (size_t)m * N + col) = make_float2(v0, v1);
            }
        }
    }
}

// ===========================================================================
// tf32 GEMM small: tiles 64 x 64 x 32, 128 threads (4 warps 2x2), 2 stages.
// ===========================================================================
template <int ACT, bool HASRES, bool HASPOS>
__global__ __launch_bounds__(128, 4)
void tgemm_s(const float* __restrict__ A, const float* __restrict__ W,
             const float* __restrict__ bias, const float* __restrict__ res,
             const float* __restrict__ pos, float* __restrict__ C,
             int M, int N, int K)
{
    extern __shared__ float dynsmem[];
    float* As_ = dynsmem;                  // [2][64][36]
    float* Bs_ = dynsmem + 2 * 64 * 36;    // [2][32][72]

    const int tid = threadIdx.x;
    const int lane = tid & 31, wid = tid >> 5;
    const int wm = wid >> 1, wn = wid & 1;
    const int m0 = blockIdx.y * 64, n0 = blockIdx.x * 64;

    float acc[2][4][4] = {};

    const int arow = tid >> 3, acol = (tid & 7) * 4;
    const int brow = tid >> 4, bcol = (tid & 15) * 4;

    const uint32_t sA = (uint32_t)__cvta_generic_to_shared(As_);
    const uint32_t sB = (uint32_t)__cvta_generic_to_shared(Bs_);

    const int ntiles = K >> 5;

    auto issue = [&](int t, int buf) {
        int kbase = t * 32;
#pragma unroll
        for (int r = 0; r < 4; r++) {
            uint32_t d = sA + (uint32_t)(((buf * 64) + arow + r * 16) * 36 + acol) * 4u;
            const float* s = A + (size_t)(m0 + arow + r * 16) * K + kbase + acol;
            CP16(d, s);
        }
#pragma unroll
        for (int r = 0; r < 4; r++) {
            uint32_t d = sB + (uint32_t)(((buf * 32) + brow + r * 8) * 72 + bcol) * 4u;
            const float* s = W + (size_t)(kbase + brow + r * 8) * N + n0 + bcol;
            CP16(d, s);
        }
        asm volatile("cp.async.commit_group;");
    };

    issue(0, 0);

    for (int t = 0; t < ntiles; t++) {
        int cur = t & 1;
        asm volatile("cp.async.wait_group 0;");
        __syncthreads();
        if (t + 1 < ntiles) issue(t + 1, cur ^ 1);

        const float* Ab = As_ + (size_t)cur * 64 * 36;
        const float* Bb = Bs_ + (size_t)cur * 32 * 72;

#pragma unroll
        for (int ks = 0; ks < 4; ks++) {
            int kk = ks * 8;
            uint32_t af[2][4], bf[4][2];
#pragma unroll
            for (int am = 0; am < 2; am++) {
                int row = wm * 32 + am * 16 + (lane >> 2);
                int k = kk + (lane & 3);
                af[am][0] = f2tf32(Ab[row * 36 + k]);
                af[am][1] = f2tf32(Ab[(row + 8) * 36 + k]);
                af[am][2] = f2tf32(Ab[row * 36 + k + 4]);
                af[am][3] = f2tf32(Ab[(row + 8) * 36 + k + 4]);
            }
#pragma unroll
            for (int an = 0; an < 4; an++) {
                int col = wn * 32 + an * 8 + (lane >> 2);
                int k = kk + (lane & 3);
                bf[an][0] = f2tf32(Bb[k * 72 + col]);
                bf[an][1] = f2tf32(Bb[(k + 4) * 72 + col]);
            }
#pragma unroll
            for (int am = 0; am < 2; am++)
#pragma unroll
                for (int an = 0; an < 4; an++)
                    MMA_TF32(acc[am][an], af[am][0], af[am][1], af[am][2], af[am][3],
                             bf[an][0], bf[an][1]);
        }
        __syncthreads();
    }

#pragma unroll
    for (int am = 0; am < 2; am++) {
#pragma unroll
        for (int an = 0; an < 4; an++) {
            int row = m0 + wm * 32 + am * 16 + (lane >> 2);
            int col = n0 + wn * 32 + an * 8 + ((lane & 3) << 1);
            float b0 = bias[col], b1 = bias[col + 1];
#pragma unroll
            for (int h = 0; h < 2; h++) {
                int m = row + h * 8;
                float v0 = apply_act(acc[am][an][h * 2 + 0] + b0, ACT);
                float v1 = apply_act(acc[am][an][h * 2 + 1] + b1, ACT);
                if (HASRES) {
                    float2 rr = *(const float2*)(res + (size_t)m * N + col);
                    v0 += rr.x; v1 += rr.y;
                }
                if (HASPOS) {
                    float2 pp = *(const float2*)(pos + (size_t)(m & 511) * N + col);
                    v0 += pp.x; v1 += pp.y;
                }
                *(float2*)(C + (size_t)m * N + col) = make_float2(v0, v1);
            }
        }
    }
}

// ===========================================================================
// fp32 SGEMM 64x64x16 — final out projection (precision margin).
// ===========================================================================
__global__ __launch_bounds__(128) void sgemm64_k(
    const float* __restrict__ A, const float* __restrict__ W,
    const float* __restrict__ bias, float* __restrict__ C,
    int M, int N, int K)
{
    __shared__ float As[16][64];
    __shared__ float Bs[16][64];

    int tid = threadIdx.x;
    int bm = blockIdx.y * 64;
    int bn = blockIdx.x * 64;
    int ty = tid >> 3, tx = tid & 7;
    int m0 = ty * 4, n0 = tx * 8;

    float acc[4][8] = {};

    int arow = tid >> 2, acol = (tid & 3) * 4;
    int brow = tid >> 4, bcol = (tid & 15) * 4;

    for (int k0 = 0; k0 < K; k0 += 16) {
#pragma unroll
        for (int r = 0; r < 2; r++) {
            float4 av = *(const float4*)(A + (size_t)(bm + arow + r * 32) * K + k0 + acol);
            As[acol + 0][arow + r * 32] = av.x;
            As[acol + 1][arow + r * 32] = av.y;
            As[acol + 2][arow + r * 32] = av.z;
            As[acol + 3][arow + r * 32] = av.w;
            float4 bv = *(const float4*)(W + (size_t)(k0 + brow + r * 8) * N + bn + bcol);
            *(float4*)(&Bs[brow + r * 8][bcol]) = bv;
        }
        __syncthreads();

#pragma unroll
        for (int k = 0; k < 16; k++) {
            float a[4], b[8];
#pragma unroll
            for (int i = 0; i < 4; i++) a[i] = As[k][m0 + i];
#pragma unroll
            for (int j = 0; j < 8; j++) b[j] = Bs[k][n0 + j];
#pragma unroll
            for (int i = 0; i < 4; i++)
#pragma unroll
                for (int j = 0; j < 8; j++)
                    acc[i][j] = fmaf(a[i], b[j], acc[i][j]);
        }
        __syncthreads();
    }

#pragma unroll
    for (int i = 0; i < 4; i++) {
        int m = bm + m0 + i;
#pragma unroll
        for (int j = 0; j < 8; j++) {
            int n = bn + n0 + j;
            C[(size_t)m * N + n] = acc[i][j] + bias[n];
        }
    }
}

// ===========================================================================
// Flash attention, 2-way key split per query + exact online-softmax merge.
// ===========================================================================
__global__ __launch_bounds__(256) void attn3_k(const float* __restrict__ c,
                                               float* __restrict__ x)
{
    const int S = 512, TD = 768;
    __shared__ float Ks[128][36];
    __shared__ float Vs[128][36];
    __shared__ float Ms[128], Ls[128];

    int qt = blockIdx.x, bh = blockIdx.y;
    int b = bh >> 3, h = bh & 7;
    int tid = threadIdx.x;
    int q = tid & 127;
    int half = tid >> 7;
    int i = qt * 128 + q;

    const float* base = c + (size_t)(b * S) * TD;
    const float scale = 0.17677669529663687f;

    float4 qv[8];
    {
        const float4* qp = (const float4*)(base + (size_t)i * TD + h * 32);
#pragma unroll
        for (int d = 0; d < 8; d++) qv[d] = qp[d];
    }

    float m = -1e30f, l = 0.0f;
    float4 acc[8];
#pragma unroll
    for (int d = 0; d < 8; d++) acc[d] = make_float4(0.f, 0.f, 0.f, 0.f);

    for (int kt = 0; kt <= qt; kt++) {
        int jbase = kt * 128;
        {
            const float4* sp = (const float4*)(base + (size_t)(jbase + q) * TD
                                               + (half ? 512 : 256) + h * 32);
            float4* dp = (float4*)(half ? &Vs[q][0] : &Ks[q][0]);
#pragma unroll
            for (int d = 0; d < 8; d++) dp[d] = sp[d];
        }
        __syncthreads();

        int jmax = (kt == qt) ? q : 127;
        for (int jj = half; jj <= jmax; jj += 2) {
            const float4* kr = (const float4*)&Ks[jj][0];
            float s0 = 0.0f, s1 = 0.0f;
#pragma unroll
            for (int d = 0; d < 8; d += 2) {
                float4 k0 = kr[d], k1 = kr[d + 1];
                s0 = fmaf(qv[d].x, k0.x, s0);
                s0 = fmaf(qv[d].y, k0.y, s0);
                s0 = fmaf(qv[d].z, k0.z, s0);
                s0 = fmaf(qv[d].w, k0.w, s0);
                s1 = fmaf(qv[d + 1].x, k1.x, s1);
                s1 = fmaf(qv[d + 1].y, k1.y, s1);
                s1 = fmaf(qv[d + 1].z, k1.z, s1);
                s1 = fmaf(qv[d + 1].w, k1.w, s1);
            }
            float s = (s0 + s1) * scale;
            const float4* vr = (const float4*)&Vs[jj][0];
            if (s <= m) {
                float p = __expf(s - m);
                l += p;
#pragma unroll
                for (int d = 0; d < 8; d++) {
                    float4 vv = vr[d];
                    acc[d].x = fmaf(p, vv.x, acc[d].x);
                    acc[d].y = fmaf(p, vv.y, acc[d].y);
                    acc[d].z = fmaf(p, vv.z, acc[d].z);
                    acc[d].w = fmaf(p, vv.w, acc[d].w);
                }
            } else {
                float corr = __expf(m - s);
                l = fmaf(l, corr, 1.0f);
#pragma unroll
                for (int d = 0; d < 8; d++) {
                    float4 vv = vr[d];
                    acc[d].x = fmaf(acc[d].x, corr, vv.x);
                    acc[d].y = fmaf(acc[d].y, corr, vv.y);
                    acc[d].z = fmaf(acc[d].z, corr, vv.z);
                    acc[d].w = fmaf(acc[d].w, corr, vv.w);
                }
                m = s;
            }
        }
        __syncthreads();
    }

    if (half == 1) {
        Ms[q] = m;
        Ls[q] = l;
        float4* dp = (float4*)&Ks[q][0];
#pragma unroll
        for (int d = 0; d < 8; d++) dp[d] = acc[d];
    }
    __syncthreads();
    if (half == 0) {
        float m1 = Ms[q], l1 = Ls[q];
        float mstar = fmaxf(m, m1);
        float c0 = __expf(m - mstar);
        float c1 = __expf(m1 - mstar);
        float lstar = l * c0 + l1 * c1;
        float inv = 1.0f / lstar;
        const float4* ap = (const float4*)&Ks[q][0];
        float4* xp = (float4*)(x + (size_t)(b * S + i) * 256 + h * 32);
#pragma unroll
        for (int d = 0; d < 8; d++) {
            float4 a1 = ap[d];
            float4 o = xp[d];
            o.x += (acc[d].x * c0 + a1.x * c1) * inv;
            o.y += (acc[d].y * c0 + a1.y * c1) * inv;
            o.z += (acc[d].z * c0 + a1.z * c1) * inv;
            o.w += (acc[d].w * c0 + a1.w * c1) * inv;
            xp[d] = o;
        }
    }
}

// ===========================================================================
// Global standardization
// ===========================================================================
__global__ void zero_stats_k() { g_sum_d = 0.0; g_sumsq_d = 0.0; }

__global__ void stats_k(const float* __restrict__ e, int n)
{
    double s = 0.0, ss = 0.0;
    for (int i = blockIdx.x * blockDim.x + threadIdx.x; i < n;
         i += gridDim.x * blockDim.x) {
        double v = (double)e[i];
        s += v;
        ss += v * v;
    }
    for (int o = 16; o > 0; o >>= 1) {
        s  += __shfl_xor_sync(0xffffffffu, s, o);
        ss += __shfl_xor_sync(0xffffffffu, ss, o);
    }
    __shared__ double rs[8], rss[8];
    int w = threadIdx.x >> 5, lid = threadIdx.x & 31;
    if (lid == 0) { rs[w] = s; rss[w] = ss; }
    __syncthreads();
    if (threadIdx.x == 0) {
        double S = 0.0, SS = 0.0;
        int nw = blockDim.x >> 5;
        for (int i = 0; i < nw; i++) { S += rs[i]; SS += rss[i]; }
        atomicAdd(&g_sum_d, S);
        atomicAdd(&g_sumsq_d, SS);
    }
}

__global__ void normfinal_k(float* e, int n)
{
    double mean = g_sum_d / (double)n;
    double var = (g_sumsq_d - (double)n * mean * mean) / (double)(n - 1);
    double inv = rsqrt(var);
    for (int i = blockIdx.x * blockDim.x + threadIdx.x; i < n;
         i += gridDim.x * blockDim.x) {
        e[i] = (float)(((double)e[i] - mean) * inv + 1e-10);
    }
}

// ===========================================================================
extern "C" void kernel_launch(void* const* d_in, const int* in_sizes, int n_in,
                              void* d_out, int out_size)
{
    const float* state = (const float*)d_in[0];
    const float* fc1w = (const float*)d_in[1];
    const float* fc1b = (const float*)d_in[2];
    const float* fc2w = (const float*)d_in[3];
    const float* fc2b = (const float*)d_in[4];
    const float* fc3w = (const float*)d_in[5];
    const float* fc3b = (const float*)d_in[6];
    const float* fc4w = (const float*)d_in[7];
    const float* fc4b = (const float*)d_in[8];
    const float* fc5w = (const float*)d_in[9];
    const float* fc5b = (const float*)d_in[10];
    const float* prew = (const float*)d_in[11];
    const float* preb = (const float*)d_in[12];
    const float* posw = (const float*)d_in[13];
    const float* encw = (const float*)d_in[14];
    const float* encb = (const float*)d_in[15];
    const float* ln1g = (const float*)d_in[16];
    const float* ln1b = (const float*)d_in[17];
    const float* ln2g = (const float*)d_in[18];
    const float* ln2b = (const float*)d_in[19];
    const float* rw1  = (const float*)d_in[20];
    const float* rb1  = (const float*)d_in[21];
    const float* rw2  = (const float*)d_in[22];
    const float* rb2  = (const float*)d_in[23];
    const float* outw = (const float*)d_in[24];
    const float* outb = (const float*)d_in[25];
    float* out = (float*)d_out;

    float *ga, *gb, *gx, *gy, *gc, *gh;
    cudaGetSymbolAddress((void**)&ga, g_a);
    cudaGetSymbolAddress((void**)&gb, g_b);
    cudaGetSymbolAddress((void**)&gx, g_x);
    cudaGetSymbolAddress((void**)&gy, g_y);
    cudaGetSymbolAddress((void**)&gc, g_c);
    cudaGetSymbolAddress((void**)&gh, g_h);

    const int M = 4096;
    const int SM128 = (2 * 128 * 36 + 2 * 32 * 136) * 4;  // 71680
    const int SM64  = (2 * 64  * 36 + 2 * 32 * 136) * 4;  // 53248
    const int SMS   = (2 * 64  * 36 + 2 * 32 * 72) * 4;   // 36864
    const int SMLN  = (64 * 260 + 2 * 32 * 136) * 4;      // 101376

    cudaFuncSetAttribute(tgemm_k<128,1,false,false>, cudaFuncAttributeMaxDynamicSharedMemorySize, SM128);
    cudaFuncSetAttribute(tgemm_k<64,1,false,false>,  cudaFuncAttributeMaxDynamicSharedMemorySize, SM64);
    cudaFuncSetAttribute(tgemm_s<2,false,false>,     cudaFuncAttributeMaxDynamicSharedMemorySize, SMS);
    cudaFuncSetAttribute(tgemm_s<0,false,true>,      cudaFuncAttributeMaxDynamicSharedMemorySize, SMS);
    cudaFuncSetAttribute(tgemm_s<0,true,false>,      cudaFuncAttributeMaxDynamicSharedMemorySize, SMS);
    cudaFuncSetAttribute(tgemm_ln_k<0,false>,        cudaFuncAttributeMaxDynamicSharedMemorySize, SMLN);
    cudaFuncSetAttribute(tgemm_ln_k<3,true>,         cudaFuncAttributeMaxDynamicSharedMemorySize, SMLN);

    // MLP funnel
    tgemm_k<128,1,false,false><<<dim3(32, 32), 256, SM128>>>(state, fc1w, fc1b, nullptr, nullptr, ga, M, 4096, 4096);
    tgemm_k<128,1,false,false><<<dim3(16, 32), 256, SM128>>>(ga, fc2w, fc2b, nullptr, nullptr, gb, M, 2048, 4096);
    tgemm_k<128,1,false,false><<<dim3(8, 32), 256, SM128>>>(gb, fc3w, fc3b, nullptr, nullptr, ga, M, 1024, 2048);
    tgemm_k<64,1,false,false><<<dim3(4, 64), 256, SM64>>>(ga, fc4w, fc4b, nullptr, nullptr, gb, M, 512, 1024);
    tgemm_s<2,false,false><<<dim3(4, 64), 128, SMS>>>(gb, fc5w, fc5b, nullptr, nullptr, ga, M, 256, 512);
    tgemm_s<0,false,true><<<dim3(4, 64), 128, SMS>>>(ga, prew, preb, nullptr, posw, gx, M, 256, 256);

    for (int l = 0; l < 8; l++) {
        // enc: LN1 fused
        tgemm_ln_k<0,false><<<dim3(6, 64), 256, SMLN>>>(gx, encw + (size_t)l * 256 * 768,
                                                        encb + l * 768, ln1g + l * 256,
                                                        ln1b + l * 256, gc, nullptr, 768);
        attn3_k<<<dim3(4, 64), 256>>>(gc, gx);
        // res1: LN2 fused; normalized stream -> gy
        tgemm_ln_k<3,true><<<dim3(8, 64), 256, SMLN>>>(gx, rw1 + (size_t)l * 256 * 1024,
                                                       rb1 + l * 1024, ln2g + l * 256,
                                                       ln2b + l * 256, gh, gy, 1024);
        // res2: stream_new = gy + mlp_out -> gx
        tgemm_s<0,true,false><<<dim3(4, 64), 128, SMS>>>(gh, rw2 + (size_t)l * 1024 * 256,
                                                         rb2 + l * 256, gy, nullptr, gx, M, 256, 1024);
    }

    // final projection in fp32, then global standardize
    sgemm64_k<<<dim3(2, 64), 128>>>(gx, outw, outb, out, M, 128, 256);
    zero_stats_k<<<1, 1>>>();
    stats_k<<<512, 256>>>(out, 4096 * 128);
    normfinal_k<<<512, 256>>>(out, 4096 * 128);
}

// round 16
// speedup vs baseline: 1.0483x; 1.0483x over previous
#include <cuda_runtime.h>
#include <math.h>
#include <stdint.h>

// ---------------------------------------------------------------------------
// AttentionEncoderModel on GB300 — R16.
// R11 core + "free pre-rounding": activations RNA-rounded at production
// (GEMM epilogues, dual-output LN), so GEMM mainloops cvt only the B
// (weight) fragments. fc1 keeps A-cvts (A = harness state). attn3 attention.
// Numerics identical to R7/R11 family: rel_err 4.6976e-4.
// ---------------------------------------------------------------------------

__device__ float g_a[4096 * 4096];
__device__ float g_b[4096 * 2048];
__device__ float g_x[4096 * 256];
__device__ float g_xn[4096 * 256];
__device__ float g_c[4096 * 768];
__device__ float g_h[4096 * 1024];
__device__ double g_sum_d, g_sumsq_d;

#define CP16(dst, src) \
    asm volatile("cp.async.ca.shared.global [%0], [%1], 16;" :: "r"(dst), "l"(src))

__device__ __forceinline__ uint32_t f2tf32(float f) {
    uint32_t u;
    asm("cvt.rna.tf32.f32 %0, %1;" : "=r"(u) : "f"(f));
    return u;
}
__device__ __forceinline__ float rnd_tf32(float f) {
    return __uint_as_float(f2tf32(f));
}

#define MMA_TF32(acc, a0, a1, a2, a3, b0, b1) \
    asm volatile( \
        "mma.sync.aligned.m16n8k8.row.col.f32.tf32.tf32.f32 " \
        "{%0,%1,%2,%3}, {%4,%5,%6,%7}, {%8,%9}, {%0,%1,%2,%3};" \
        : "+f"((acc)[0]), "+f"((acc)[1]), "+f"((acc)[2]), "+f"((acc)[3]) \
        : "r"(a0), "r"(a1), "r"(a2), "r"(a3), "r"(b0), "r"(b1))

__device__ __forceinline__ float apply_act(float v, int ACT) {
    if (ACT == 1) return fmaxf(v, 0.0f);
    if (ACT == 2) return tanhf(v);
    if (ACT == 3) return 0.5f * v * (1.0f + erff(v * 0.70710678118654752f));
    return v;
}

// ===========================================================================
// tf32 GEMM, tiles BMT x 128 x 32, 256 threads, 2-stage cp.async.
// CVTA: cvt A-fragments in-loop (only fc1 needs it). B always cvt'd in-loop.
// ROUND: RNA-round epilogue values (before residual/pos add).
// ===========================================================================
template <int BMT, int ACT, bool HASRES, bool HASPOS, bool CVTA, bool ROUND>
__global__ __launch_bounds__(256, 2)
void tgemm_k(const float* __restrict__ A, const float* __restrict__ W,
             const float* __restrict__ bias, const float* __restrict__ res,
             const float* __restrict__ pos, float* __restrict__ C,
             int M, int N, int K)
{
    constexpr int AM = BMT / 32;
    extern __shared__ float dynsmem[];
    float* As_ = dynsmem;                   // [2][BMT][36]
    float* Bs_ = dynsmem + 2 * BMT * 36;    // [2][32][136]

    const int tid = threadIdx.x;
    const int lane = tid & 31, wid = tid >> 5;
    const int wm = wid >> 2, wn = wid & 3;
    const int m0 = blockIdx.y * BMT, n0 = blockIdx.x * 128;

    float acc[AM][4][4] = {};

    const int arow = tid >> 3, acol = (tid & 7) * 4;
    const int brow = tid >> 5, bcol = (tid & 31) * 4;

    const uint32_t sA = (uint32_t)__cvta_generic_to_shared(As_);
    const uint32_t sB = (uint32_t)__cvta_generic_to_shared(Bs_);

    const int ntiles = K >> 5;

    auto issue = [&](int t, int buf) {
        int kbase = t * 32;
#pragma unroll
        for (int r = 0; r < AM; r++) {
            uint32_t d = sA + (uint32_t)(((buf * BMT) + arow + r * 32) * 36 + acol) * 4u;
            const float* s = A + (size_t)(m0 + arow + r * 32) * K + kbase + acol;
            CP16(d, s);
        }
#pragma unroll
        for (int r = 0; r < 4; r++) {
            uint32_t d = sB + (uint32_t)(((buf * 32) + brow + r * 8) * 136 + bcol) * 4u;
            const float* s = W + (size_t)(kbase + brow + r * 8) * N + n0 + bcol;
            CP16(d, s);
        }
        asm volatile("cp.async.commit_group;");
    };

    auto lda = [&](const float* p) -> uint32_t {
        return CVTA ? f2tf32(*p) : __float_as_uint(*p);
    };

    issue(0, 0);

    for (int t = 0; t < ntiles; t++) {
        int cur = t & 1;
        asm volatile("cp.async.wait_group 0;");
        __syncthreads();
        if (t + 1 < ntiles) issue(t + 1, cur ^ 1);

        const float* Ab = As_ + (size_t)cur * BMT * 36;
        const float* Bb = Bs_ + (size_t)cur * 32 * 136;

#pragma unroll
        for (int ks = 0; ks < 4; ks++) {
            int kk = ks * 8;
            uint32_t af[AM][4], bf[4][2];
#pragma unroll
            for (int am = 0; am < AM; am++) {
                int row = wm * (BMT / 2) + am * 16 + (lane >> 2);
                int k = kk + (lane & 3);
                af[am][0] = lda(&Ab[row * 36 + k]);
                af[am][1] = lda(&Ab[(row + 8) * 36 + k]);
                af[am][2] = lda(&Ab[row * 36 + k + 4]);
                af[am][3] = lda(&Ab[(row + 8) * 36 + k + 4]);
            }
#pragma unroll
            for (int an = 0; an < 4; an++) {
                int col = wn * 32 + an * 8 + (lane >> 2);
                int k = kk + (lane & 3);
                bf[an][0] = f2tf32(Bb[k * 136 + col]);
                bf[an][1] = f2tf32(Bb[(k + 4) * 136 + col]);
            }
#pragma unroll
            for (int am = 0; am < AM; am++)
#pragma unroll
                for (int an = 0; an < 4; an++)
                    MMA_TF32(acc[am][an], af[am][0], af[am][1], af[am][2], af[am][3],
                             bf[an][0], bf[an][1]);
        }
        __syncthreads();
    }

#pragma unroll
    for (int am = 0; am < AM; am++) {
#pragma unroll
        for (int an = 0; an < 4; an++) {
            int row = m0 + wm * (BMT / 2) + am * 16 + (lane >> 2);
            int col = n0 + wn * 32 + an * 8 + ((lane & 3) << 1);
            float b0 = bias[col], b1 = bias[col + 1];
#pragma unroll
            for (int h = 0; h < 2; h++) {
                int m = row + h * 8;
                float v0 = apply_act(acc[am][an][h * 2 + 0] + b0, ACT);
                float v1 = apply_act(acc[am][an][h * 2 + 1] + b1, ACT);
                if (ROUND) { v0 = rnd_tf32(v0); v1 = rnd_tf32(v1); }
                if (HASRES) {
                    float2 rr = *(const float2*)(res + (size_t)m * N + col);
                    v0 += rr.x; v1 += rr.y;
                }
                if (HASPOS) {
                    float2 pp = *(const float2*)(pos + (size_t)(m & 511) * N + col);
                    v0 += pp.x; v1 += pp.y;
                }
                *(float2*)(C + (size_t)m * N + col) = make_float2(v0, v1);
            }
        }
    }
}

// ===========================================================================
// tf32 GEMM small: tiles 64 x 64 x 32, 128 threads, 2 stages.
// A assumed pre-rounded; B cvt'd in-loop. ROUND rounds epilogue.
// ===========================================================================
template <int ACT, bool HASRES, bool HASPOS, bool ROUND>
__global__ __launch_bounds__(128, 4)
void tgemm_s(const float* __restrict__ A, const float* __restrict__ W,
             const float* __restrict__ bias, const float* __restrict__ res,
             const float* __restrict__ pos, float* __restrict__ C,
             int M, int N, int K)
{
    extern __shared__ float dynsmem[];
    float* As_ = dynsmem;                  // [2][64][36]
    float* Bs_ = dynsmem + 2 * 64 * 36;    // [2][32][72]

    const int tid = threadIdx.x;
    const int lane = tid & 31, wid = tid >> 5;
    const int wm = wid >> 1, wn = wid & 1;
    const int m0 = blockIdx.y * 64, n0 = blockIdx.x * 64;

    float acc[2][4][4] = {};

    const int arow = tid >> 3, acol = (tid & 7) * 4;
    const int brow = tid >> 4, bcol = (tid & 15) * 4;

    const uint32_t sA = (uint32_t)__cvta_generic_to_shared(As_);
    const uint32_t sB = (uint32_t)__cvta_generic_to_shared(Bs_);

    const int ntiles = K >> 5;

    auto issue = [&](int t, int buf) {
        int kbase = t * 32;
#pragma unroll
        for (int r = 0; r < 4; r++) {
            uint32_t d = sA + (uint32_t)(((buf * 64) + arow + r * 16) * 36 + acol) * 4u;
            const float* s = A + (size_t)(m0 + arow + r * 16) * K + kbase + acol;
            CP16(d, s);
        }
#pragma unroll
        for (int r = 0; r < 4; r++) {
            uint32_t d = sB + (uint32_t)(((buf * 32) + brow + r * 8) * 72 + bcol) * 4u;
            const float* s = W + (size_t)(kbase + brow + r * 8) * N + n0 + bcol;
            CP16(d, s);
        }
        asm volatile("cp.async.commit_group;");
    };

    issue(0, 0);

    for (int t = 0; t < ntiles; t++) {
        int cur = t & 1;
        asm volatile("cp.async.wait_group 0;");
        __syncthreads();
        if (t + 1 < ntiles) issue(t + 1, cur ^ 1);

        const float* Ab = As_ + (size_t)cur * 64 * 36;
        const float* Bb = Bs_ + (size_t)cur * 32 * 72;

#pragma unroll
        for (int ks = 0; ks < 4; ks++) {
            int kk = ks * 8;
            uint32_t af[2][4], bf[4][2];
#pragma unroll
            for (int am = 0; am < 2; am++) {
                int row = wm * 32 + am * 16 + (lane >> 2);
                int k = kk + (lane & 3);
                af[am][0] = __float_as_uint(Ab[row * 36 + k]);
                af[am][1] = __float_as_uint(Ab[(row + 8) * 36 + k]);
                af[am][2] = __float_as_uint(Ab[row * 36 + k + 4]);
                af[am][3] = __float_as_uint(Ab[(row + 8) * 36 + k + 4]);
            }
#pragma unroll
            for (int an = 0; an < 4; an++) {
                int col = wn * 32 + an * 8 + (lane >> 2);
                int k = kk + (lane & 3);
                bf[an][0] = f2tf32(Bb[k * 72 + col]);
                bf[an][1] = f2tf32(Bb[(k + 4) * 72 + col]);
            }
#pragma unroll
            for (int am = 0; am < 2; am++)
#pragma unroll
                for (int an = 0; an < 4; an++)
                    MMA_TF32(acc[am][an], af[am][0], af[am][1], af[am][2], af[am][3],
                             bf[an][0], bf[an][1]);
        }
        __syncthreads();
    }

#pragma unroll
    for (int am = 0; am < 2; am++) {
#pragma unroll
        for (int an = 0; an < 4; an++) {
            int row = m0 + wm * 32 + am * 16 + (lane >> 2);
            int col = n0 + wn * 32 + an * 8 + ((lane & 3) << 1);
            float b0 = bias[col], b1 = bias[col + 1];
#pragma unroll
            for (int h = 0; h < 2; h++) {
                int m = row + h * 8;
                float v0 = apply_act(acc[am][an][h * 2 + 0] + b0, ACT);
                float v1 = apply_act(acc[am][an][h * 2 + 1] + b1, ACT);
                if (ROUND) { v0 = rnd_tf32(v0); v1 = rnd_tf32(v1); }
                if (HASRES) {
                    float2 rr = *(const float2*)(res + (size_t)m * N + col);
                    v0 += rr.x; v1 += rr.y;
                }
                if (HASPOS) {
                    float2 pp = *(const float2*)(pos + (size_t)(m & 511) * N + col);
                    v0 += pp.x; v1 += pp.y;
                }
                *(float2*)(C + (size_t)m * N + col) = make_float2(v0, v1);
            }
        }
    }
}

// ===========================================================================
// fp32 SGEMM 64x64x16 — final out projection (precision margin).
// ===========================================================================
__global__ __launch_bounds__(128) void sgemm64_k(
    const float* __restrict__ A, const float* __restrict__ W,
    const float* __restrict__ bias, float* __restrict__ C,
    int M, int N, int K)
{
    __shared__ float As[16][64];
    __shared__ float Bs[16][64];

    int tid = threadIdx.x;
    int bm = blockIdx.y * 64;
    int bn = blockIdx.x * 64;
    int ty = tid >> 3, tx = tid & 7;
    int m0 = ty * 4, n0 = tx * 8;

    float acc[4][8] = {};

    int arow = tid >> 2, acol = (tid & 3) * 4;
    int brow = tid >> 4, bcol = (tid & 15) * 4;

    for (int k0 = 0; k0 < K; k0 += 16) {
#pragma unroll
        for (int r = 0; r < 2; r++) {
            float4 av = *(const float4*)(A + (size_t)(bm + arow + r * 32) * K + k0 + acol);
            As[acol + 0][arow + r * 32] = av.x;
            As[acol + 1][arow + r * 32] = av.y;
            As[acol + 2][arow + r * 32] = av.z;
            As[acol + 3][arow + r * 32] = av.w;
            float4 bv = *(const float4*)(W + (size_t)(k0 + brow + r * 8) * N + bn + bcol);
            *(float4*)(&Bs[brow + r * 8][bcol]) = bv;
        }
        __syncthreads();

#pragma unroll
        for (int k = 0; k < 16; k++) {
            float a[4], b[8];
#pragma unroll
            for (int i = 0; i < 4; i++) a[i] = As[k][m0 + i];
#pragma unroll
            for (int j = 0; j < 8; j++) b[j] = Bs[k][n0 + j];
#pragma unroll
            for (int i = 0; i < 4; i++)
#pragma unroll
                for (int j = 0; j < 8; j++)
                    acc[i][j] = fmaf(a[i], b[j], acc[i][j]);
        }
        __syncthreads();
    }

#pragma unroll
    for (int i = 0; i < 4; i++) {
        int m = bm + m0 + i;
#pragma unroll
        for (int j = 0; j < 8; j++) {
            int n = bn + n0 + j;
            C[(size_t)m * N + n] = acc[i][j] + bias[n];
        }
    }
}

// ===========================================================================
// LayerNorm D=256: warp per row. y = ROUNDED (GEMM input); y2 = exact if DUAL.
// ===========================================================================
template <bool DUAL>
__global__ __launch_bounds__(256) void layernorm8_k(
    const float* __restrict__ x, const float* __restrict__ g,
    const float* __restrict__ b, float* __restrict__ y, float* __restrict__ y2)
{
    int w = threadIdx.x >> 5, lane = threadIdx.x & 31;
    size_t r = (size_t)blockIdx.x * 8 + w;
    const float4* xp = (const float4*)(x + r * 256);
    float4 v0 = xp[lane];
    float4 v1 = xp[lane + 32];

    float s = v0.x + v0.y + v0.z + v0.w + v1.x + v1.y + v1.z + v1.w;
#pragma unroll
    for (int o = 16; o > 0; o >>= 1) s += __shfl_xor_sync(0xffffffffu, s, o);
    float mean = s * (1.0f / 256.0f);

    float d0x = v0.x - mean, d0y = v0.y - mean, d0z = v0.z - mean, d0w = v0.w - mean;
    float d1x = v1.x - mean, d1y = v1.y - mean, d1z = v1.z - mean, d1w = v1.w - mean;
    float ss = d0x * d0x + d0y * d0y + d0z * d0z + d0w * d0w
             + d1x * d1x + d1y * d1y + d1z * d1z + d1w * d1w;
#pragma unroll
    for (int o = 16; o > 0; o >>= 1) ss += __shfl_xor_sync(0xffffffffu, ss, o);
    float inv = rsqrtf(ss * (1.0f / 256.0f) + 1e-5f);

    float4 g0 = ((const float4*)g)[lane], g1 = ((const float4*)g)[lane + 32];
    float4 b0 = ((const float4*)b)[lane], b1 = ((const float4*)b)[lane + 32];
    float4 o0 = make_float4(d0x * inv * g0.x + b0.x, d0y * inv * g0.y + b0.y,
                            d0z * inv * g0.z + b0.z, d0w * inv * g0.w + b0.w);
    float4 o1 = make_float4(d1x * inv * g1.x + b1.x, d1y * inv * g1.y + b1.y,
                            d1z * inv * g1.z + b1.z, d1w * inv * g1.w + b1.w);
    if (DUAL) {
        float4* y2p = (float4*)(y2 + r * 256);
        y2p[lane] = o0;
        y2p[lane + 32] = o1;
    }
    float4* yp = (float4*)(y + r * 256);
    yp[lane] = make_float4(rnd_tf32(o0.x), rnd_tf32(o0.y), rnd_tf32(o0.z), rnd_tf32(o0.w));
    yp[lane + 32] = make_float4(rnd_tf32(o1.x), rnd_tf32(o1.y), rnd_tf32(o1.z), rnd_tf32(o1.w));
}

// ===========================================================================
// Flash attention, 2-way key split per query + exact online-softmax merge.
// ===========================================================================
__global__ __launch_bounds__(256) void attn3_k(const float* __restrict__ c,
                                               float* __restrict__ x)
{
    const int S = 512, TD = 768;
    __shared__ float Ks[128][36];
    __shared__ float Vs[128][36];
    __shared__ float Ms[128], Ls[128];

    int qt = blockIdx.x, bh = blockIdx.y;
    int b = bh >> 3, h = bh & 7;
    int tid = threadIdx.x;
    int q = tid & 127;
    int half = tid >> 7;
    int i = qt * 128 + q;

    const float* base = c + (size_t)(b * S) * TD;
    const float scale = 0.17677669529663687f;

    float4 qv[8];
    {
        const float4* qp = (const float4*)(base + (size_t)i * TD + h * 32);
#pragma unroll
        for (int d = 0; d < 8; d++) qv[d] = qp[d];
    }

    float m = -1e30f, l = 0.0f;
    float4 acc[8];
#pragma unroll
    for (int d = 0; d < 8; d++) acc[d] = make_float4(0.f, 0.f, 0.f, 0.f);

    for (int kt = 0; kt <= qt; kt++) {
        int jbase = kt * 128;
        {
            const float4* sp = (const float4*)(base + (size_t)(jbase + q) * TD
                                               + (half ? 512 : 256) + h * 32);
            float4* dp = (float4*)(half ? &Vs[q][0] : &Ks[q][0]);
#pragma unroll
            for (int d = 0; d < 8; d++) dp[d] = sp[d];
        }
        __syncthreads();

        int jmax = (kt == qt) ? q : 127;
        for (int jj = half; jj <= jmax; jj += 2) {
            const float4* kr = (const float4*)&Ks[jj][0];
            float s0 = 0.0f, s1 = 0.0f;
#pragma unroll
            for (int d = 0; d < 8; d += 2) {
                float4 k0 = kr[d], k1 = kr[d + 1];
                s0 = fmaf(qv[d].x, k0.x, s0);
                s0 = fmaf(qv[d].y, k0.y, s0);
                s0 = fmaf(qv[d].z, k0.z, s0);
                s0 = fmaf(qv[d].w, k0.w, s0);
                s1 = fmaf(qv[d + 1].x, k1.x, s1);
                s1 = fmaf(qv[d + 1].y, k1.y, s1);
                s1 = fmaf(qv[d + 1].z, k1.z, s1);
                s1 = fmaf(qv[d + 1].w, k1.w, s1);
            }
            float s = (s0 + s1) * scale;
            const float4* vr = (const float4*)&Vs[jj][0];
            if (s <= m) {
                float p = __expf(s - m);
                l += p;
#pragma unroll
                for (int d = 0; d < 8; d++) {
                    float4 vv = vr[d];
                    acc[d].x = fmaf(p, vv.x, acc[d].x);
                    acc[d].y = fmaf(p, vv.y, acc[d].y);
                    acc[d].z = fmaf(p, vv.z, acc[d].z);
                    acc[d].w = fmaf(p, vv.w, acc[d].w);
                }
            } else {
                float corr = __expf(m - s);
                l = fmaf(l, corr, 1.0f);
#pragma unroll
                for (int d = 0; d < 8; d++) {
                    float4 vv = vr[d];
                    acc[d].x = fmaf(acc[d].x, corr, vv.x);
                    acc[d].y = fmaf(acc[d].y, corr, vv.y);
                    acc[d].z = fmaf(acc[d].z, corr, vv.z);
                    acc[d].w = fmaf(acc[d].w, corr, vv.w);
                }
                m = s;
            }
        }
        __syncthreads();
    }

    if (half == 1) {
        Ms[q] = m;
        Ls[q] = l;
        float4* dp = (float4*)&Ks[q][0];
#pragma unroll
        for (int d = 0; d < 8; d++) dp[d] = acc[d];
    }
    __syncthreads();
    if (half == 0) {
        float m1 = Ms[q], l1 = Ls[q];
        float mstar = fmaxf(m, m1);
        float c0 = __expf(m - mstar);
        float c1 = __expf(m1 - mstar);
        float lstar = l * c0 + l1 * c1;
        float inv = 1.0f / lstar;
        const float4* ap = (const float4*)&Ks[q][0];
        float4* xp = (float4*)(x + (size_t)(b * S + i) * 256 + h * 32);
#pragma unroll
        for (int d = 0; d < 8; d++) {
            float4 a1 = ap[d];
            float4 o = xp[d];
            o.x += (acc[d].x * c0 + a1.x * c1) * inv;
            o.y += (acc[d].y * c0 + a1.y * c1) * inv;
            o.z += (acc[d].z * c0 + a1.z * c1) * inv;
            o.w += (acc[d].w * c0 + a1.w * c1) * inv;
            xp[d] = o;
        }
    }
}

// ===========================================================================
// Global standardization
// ===========================================================================
__global__ void zero_stats_k() { g_sum_d = 0.0; g_sumsq_d = 0.0; }

__global__ void stats_k(const float* __restrict__ e, int n)
{
    double s = 0.0, ss = 0.0;
    for (int i = blockIdx.x * blockDim.x + threadIdx.x; i < n;
         i += gridDim.x * blockDim.x) {
        double v = (double)e[i];
        s += v;
        ss += v * v;
    }
    for (int o = 16; o > 0; o >>= 1) {
        s  += __shfl_xor_sync(0xffffffffu, s, o);
        ss += __shfl_xor_sync(0xffffffffu, ss, o);
    }
    __shared__ double rs[8], rss[8];
    int w = threadIdx.x >> 5, lid = threadIdx.x & 31;
    if (lid == 0) { rs[w] = s; rss[w] = ss; }
    __syncthreads();
    if (threadIdx.x == 0) {
        double S = 0.0, SS = 0.0;
        int nw = blockDim.x >> 5;
        for (int i = 0; i < nw; i++) { S += rs[i]; SS += rss[i]; }
        atomicAdd(&g_sum_d, S);
        atomicAdd(&g_sumsq_d, SS);
    }
}

__global__ void normfinal_k(float* e, int n)
{
    double mean = g_sum_d / (double)n;
    double var = (g_sumsq_d - (double)n * mean * mean) / (double)(n - 1);
    double inv = rsqrt(var);
    for (int i = blockIdx.x * blockDim.x + threadIdx.x; i < n;
         i += gridDim.x * blockDim.x) {
        e[i] = (float)(((double)e[i] - mean) * inv + 1e-10);
    }
}

// ===========================================================================
extern "C" void kernel_launch(void* const* d_in, const int* in_sizes, int n_in,
                              void* d_out, int out_size)
{
    const float* state = (const float*)d_in[0];
    const float* fc1w = (const float*)d_in[1];
    const float* fc1b = (const float*)d_in[2];
    const float* fc2w = (const float*)d_in[3];
    const float* fc2b = (const float*)d_in[4];
    const float* fc3w = (const float*)d_in[5];
    const float* fc3b = (const float*)d_in[6];
    const float* fc4w = (const float*)d_in[7];
    const float* fc4b = (const float*)d_in[8];
    const float* fc5w = (const float*)d_in[9];
    const float* fc5b = (const float*)d_in[10];
    const float* prew = (const float*)d_in[11];
    const float* preb = (const float*)d_in[12];
    const float* posw = (const float*)d_in[13];
    const float* encw = (const float*)d_in[14];
    const float* encb = (const float*)d_in[15];
    const float* ln1g = (const float*)d_in[16];
    const float* ln1b = (const float*)d_in[17];
    const float* ln2g = (const float*)d_in[18];
    const float* ln2b = (const float*)d_in[19];
    const float* rw1  = (const float*)d_in[20];
    const float* rb1  = (const float*)d_in[21];
    const float* rw2  = (const float*)d_in[22];
    const float* rb2  = (const float*)d_in[23];
    const float* outw = (const float*)d_in[24];
    const float* outb = (const float*)d_in[25];
    float* out = (float*)d_out;

    float *ga, *gb, *gx, *gxn, *gc, *gh;
    cudaGetSymbolAddress((void**)&ga,  g_a);
    cudaGetSymbolAddress((void**)&gb,  g_b);
    cudaGetSymbolAddress((void**)&gx,  g_x);
    cudaGetSymbolAddress((void**)&gxn, g_xn);
    cudaGetSymbolAddress((void**)&gc,  g_c);
    cudaGetSymbolAddress((void**)&gh,  g_h);

    const int M = 4096;
    const int SM128 = (2 * 128 * 36 + 2 * 32 * 136) * 4;  // 71680
    const int SM64  = (2 * 64  * 36 + 2 * 32 * 136) * 4;  // 53248
    const int SMS   = (2 * 64  * 36 + 2 * 32 * 72) * 4;   // 36864

    cudaFuncSetAttribute(tgemm_k<128,1,false,false,true,true>,   cudaFuncAttributeMaxDynamicSharedMemorySize, SM128);
    cudaFuncSetAttribute(tgemm_k<128,1,false,false,false,true>,  cudaFuncAttributeMaxDynamicSharedMemorySize, SM128);
    cudaFuncSetAttribute(tgemm_k<128,3,false,false,false,true>,  cudaFuncAttributeMaxDynamicSharedMemorySize, SM128);
    cudaFuncSetAttribute(tgemm_k<64,1,false,false,false,true>,   cudaFuncAttributeMaxDynamicSharedMemorySize, SM64);
    cudaFuncSetAttribute(tgemm_k<64,0,false,false,false,false>,  cudaFuncAttributeMaxDynamicSharedMemorySize, SM64);
    cudaFuncSetAttribute(tgemm_s<2,false,false,true>,            cudaFuncAttributeMaxDynamicSharedMemorySize, SMS);
    cudaFuncSetAttribute(tgemm_s<0,false,true,false>,            cudaFuncAttributeMaxDynamicSharedMemorySize, SMS);
    cudaFuncSetAttribute(tgemm_s<0,true,false,false>,            cudaFuncAttributeMaxDynamicSharedMemorySize, SMS);

    // MLP funnel. fc1: A = harness state -> CVTA in-loop. Outputs rounded.
    tgemm_k<128,1,false,false,true,true><<<dim3(32, 32), 256, SM128>>>(state, fc1w, fc1b, nullptr, nullptr, ga, M, 4096, 4096);
    tgemm_k<128,1,false,false,false,true><<<dim3(16, 32), 256, SM128>>>(ga, fc2w, fc2b, nullptr, nullptr, gb, M, 2048, 4096);
    tgemm_k<128,1,false,false,false,true><<<dim3(8, 32), 256, SM128>>>(gb, fc3w, fc3b, nullptr, nullptr, ga, M, 1024, 2048);
    tgemm_k<64,1,false,false,false,true><<<dim3(4, 64), 256, SM64>>>(ga, fc4w, fc4b, nullptr, nullptr, gb, M, 512, 1024);
    tgemm_s<2,false,false,true><<<dim3(4, 64), 128, SMS>>>(gb, fc5w, fc5b, nullptr, nullptr, ga, M, 256, 512);
    // pre: output is the residual stream (exact; LN rounds before GEMM use)
    tgemm_s<0,false,true,false><<<dim3(4, 64), 128, SMS>>>(ga, prew, preb, nullptr, posw, gx, M, 256, 256);

    for (int l = 0; l < 8; l++) {
        layernorm8_k<false><<<512, 256>>>(gx, ln1g + l * 256, ln1b + l * 256, gxn, nullptr);
        tgemm_k<64,0,false,false,false,false><<<dim3(6, 64), 256, SM64>>>(gxn, encw + (size_t)l * 256 * 768,
                                                                          encb + l * 768, nullptr, nullptr, gc, M, 768, 256);
        attn3_k<<<dim3(4, 64), 256>>>(gc, gx);
        // LN2: rounded -> gxn (res1 input), exact -> gx (residual)
        layernorm8_k<true><<<512, 256>>>(gx, ln2g + l * 256, ln2b + l * 256, gxn, gx);
        tgemm_k<128,3,false,false,false,true><<<dim3(8, 32), 256, SM128>>>(gxn, rw1 + (size_t)l * 256 * 1024,
                                                                           rb1 + l * 1024, nullptr, nullptr, gh, M, 1024, 256);
        tgemm_s<0,true,false,false><<<dim3(4, 64), 128, SMS>>>(gh, rw2 + (size_t)l * 1024 * 256,
                                                               rb2 + l * 256, gx, nullptr, gx, M, 256, 1024);
    }

    // final projection in fp32, then global standardize
    sgemm64_k<<<dim3(2, 64), 128>>>(gx, outw, outb, out, M, 128, 256);
    zero_stats_k<<<1, 1>>>();
    stats_k<<<512, 256>>>(out, 4096 * 128);
    normfinal_k<<<512, 256>>>(out, 4096 * 128);
}